// round 12
// baseline (speedup 1.0000x reference)
#include <cuda_runtime.h>
#include <cuda_bf16.h>
#include <cstdint>

#define N_NODES 10000
#define N_EDGES 640000
#define D_FEAT  128

// Padded-bucket CSR: fixed capacity per node, filled by one atomic pass.
// Degrees ~ Poisson(64); P(deg >= 160) is astronomically small.
#define CAP 160

// g_cnt is zeroed at module load (.bss) and re-zeroed by fused_kernel's
// epilogue each call, so no separate zero kernel is needed.
__device__ int g_cnt[N_NODES];                 // per-node cursor / final count
__device__ int g_eid2[N_NODES * CAP];          // 6.4 MB edge-id buckets

// ---------------------------------------------------------------------------
// 1. fill buckets: single atomic pass (no histogram, no scan).
// ---------------------------------------------------------------------------
__global__ void fill_kernel(const int* __restrict__ recv_idx) {
    int i = blockIdx.x * blockDim.x + threadIdx.x;   // quad index
    if (i < N_EDGES / 4) {
        int4 r = reinterpret_cast<const int4*>(recv_idx)[i];
        int e0 = i * 4;
        int p0 = atomicAdd(&g_cnt[r.x], 1);
        int p1 = atomicAdd(&g_cnt[r.y], 1);
        int p2 = atomicAdd(&g_cnt[r.z], 1);
        int p3 = atomicAdd(&g_cnt[r.w], 1);
        g_eid2[r.x * CAP + p0] = e0;
        g_eid2[r.y * CAP + p1] = e0 + 1;
        g_eid2[r.z * CAP + p2] = e0 + 2;
        g_eid2[r.w * CAP + p3] = e0 + 3;
    }
}

// ---------------------------------------------------------------------------
// f32x2 helpers (sm_103a packed fp32 pipe: halves FMA instruction count)
// ---------------------------------------------------------------------------
__device__ __forceinline__ unsigned long long fma2(unsigned long long a,
                                                   unsigned long long b,
                                                   unsigned long long c) {
    unsigned long long d;
    asm("fma.rn.f32x2 %0, %1, %2, %3;" : "=l"(d) : "l"(a), "l"(b), "l"(c));
    return d;
}
__device__ __forceinline__ unsigned long long dup2(float x) {
    unsigned long long d;
    asm("mov.b64 %0, {%1, %1};" : "=l"(d) : "f"(x));
    return d;
}

// ---------------------------------------------------------------------------
// 2. fused gather (segment-sum) + [node_feat | agg] @ W + b
// NT=16 nodes/block, 256 threads -> 625 blocks (~4.2/SM resident, occ ~53%):
// R10 ncu showed occ=25.9% (grid-limited) with DRAM=54.5%; doubling resident
// warps doubles in-flight gather bytes.
//   Phase A: warps pop nodes from a smem ticket queue; eids staged to smem
//     (indirection = LDS->LDG); 16 edge rows (8KB) issued per iteration.
//   Phase B: tiled GEMM, K chunks of 16, f32x2 inner loop, 2 nodes/thread.
//   Epilogue re-zeros this block's g_cnt entries for the next call.
// ---------------------------------------------------------------------------
#define NT 16
#define KC 16

__global__ __launch_bounds__(256) void fused_kernel(
    const float* __restrict__ edge_feat,
    const float* __restrict__ node_feat,
    const float* __restrict__ W,
    const float* __restrict__ b,
    float* __restrict__ out)
{
    __shared__ __align__(16) float AggS[NT * D_FEAT];   //  8 KB
    __shared__ __align__(16) float Ws[KC * D_FEAT];     //  8 KB
    __shared__ __align__(16) float Xs[NT * KC];         //  1 KB
    __shared__ int eidS[8][CAP];                        //  5 KB
    __shared__ int qctr;                                // node ticket queue

    const int tid  = threadIdx.x;
    const int lane = tid & 31;
    const int wid  = tid >> 5;            // 0..7
    const int n0   = blockIdx.x * NT;

    if (tid == 0) qctr = 0;
    __syncthreads();

    // ---------------- Phase A: gather (dynamic queue) ----------------
    for (;;) {
        int pos;
        if (lane == 0) pos = atomicAdd(&qctr, 1);
        pos = __shfl_sync(0xFFFFFFFFu, pos, 0);
        if (pos >= NT) break;

        int gn = n0 + pos;
        float4 acc = make_float4(0.f, 0.f, 0.f, 0.f);
        if (gn < N_NODES) {
            const int* bucket = g_eid2 + (size_t)gn * CAP;
            int cnt = g_cnt[gn];
            if (cnt > CAP) cnt = CAP;
            // Stage eids: coalesced LDG.32 across lanes
            for (int base = lane; base < cnt; base += 32)
                eidS[wid][base] = bucket[base];
            __syncwarp();

            int t = 0;
            // 16-wide: two independent 8-batches in flight per iteration
            for (; t + 16 <= cnt; t += 16) {
                int ea[8], eb[8];
                #pragma unroll
                for (int u = 0; u < 8; u++) ea[u] = eidS[wid][t + u];
                #pragma unroll
                for (int u = 0; u < 8; u++) eb[u] = eidS[wid][t + 8 + u];
                float4 va[8], vb[8];
                #pragma unroll
                for (int u = 0; u < 8; u++)
                    va[u] = *reinterpret_cast<const float4*>(
                        edge_feat + (size_t)ea[u] * D_FEAT + lane * 4);
                #pragma unroll
                for (int u = 0; u < 8; u++)
                    vb[u] = *reinterpret_cast<const float4*>(
                        edge_feat + (size_t)eb[u] * D_FEAT + lane * 4);
                #pragma unroll
                for (int u = 0; u < 8; u++) {
                    acc.x += va[u].x; acc.y += va[u].y;
                    acc.z += va[u].z; acc.w += va[u].w;
                }
                #pragma unroll
                for (int u = 0; u < 8; u++) {
                    acc.x += vb[u].x; acc.y += vb[u].y;
                    acc.z += vb[u].z; acc.w += vb[u].w;
                }
            }
            for (; t + 4 <= cnt; t += 4) {
                int e[4];
                #pragma unroll
                for (int u = 0; u < 4; u++) e[u] = eidS[wid][t + u];
                float4 v[4];
                #pragma unroll
                for (int u = 0; u < 4; u++)
                    v[u] = *reinterpret_cast<const float4*>(
                        edge_feat + (size_t)e[u] * D_FEAT + lane * 4);
                #pragma unroll
                for (int u = 0; u < 4; u++) {
                    acc.x += v[u].x; acc.y += v[u].y;
                    acc.z += v[u].z; acc.w += v[u].w;
                }
            }
            for (; t < cnt; t++) {
                int e = eidS[wid][t];
                float4 v = *reinterpret_cast<const float4*>(
                    edge_feat + (size_t)e * D_FEAT + lane * 4);
                acc.x += v.x; acc.y += v.y; acc.z += v.z; acc.w += v.w;
            }
            __syncwarp();   // eidS reused by next popped node
        }
        *reinterpret_cast<float4*>(&AggS[pos * D_FEAT + lane * 4]) = acc;
    }
    __syncthreads();

    // Re-zero this block's cursors for the next kernel_launch call.
    if (tid < NT) {
        int gn = n0 + tid;
        if (gn < N_NODES) g_cnt[gn] = 0;
    }

    // ---------------- Phase B: GEMM (f32x2), 2 nodes per thread ----------
    unsigned long long acc2[2][2];
    acc2[0][0] = acc2[0][1] = acc2[1][0] = acc2[1][1] = 0ull;

    // First half: K in [0,128) from node_feat
    for (int k0 = 0; k0 < D_FEAT; k0 += KC) {
        {   // stage W[k0 : k0+KC, :]  (512 float4 / 256 threads)
            const float4* src = reinterpret_cast<const float4*>(W + k0 * D_FEAT);
            float4* dst = reinterpret_cast<float4*>(Ws);
            dst[tid]       = src[tid];
            dst[tid + 256] = src[tid + 256];
        }
        {   // stage X tile: 256 elements = 1 per thread
            int n = tid >> 4;         // / KC
            int k = tid & (KC - 1);
            int gn = n0 + n;
            Xs[tid] = (gn < N_NODES) ? node_feat[(size_t)gn * D_FEAT + k0 + k] : 0.f;
        }
        __syncthreads();
        #pragma unroll
        for (int kk = 0; kk < KC; kk++) {
            const unsigned long long* wrow =
                reinterpret_cast<const unsigned long long*>(&Ws[kk * D_FEAT + lane * 4]);
            unsigned long long wp0 = wrow[0];
            unsigned long long wp1 = wrow[1];
            #pragma unroll
            for (int n = 0; n < 2; n++) {
                unsigned long long xx = dup2(Xs[(wid * 2 + n) * KC + kk]);
                acc2[n][0] = fma2(xx, wp0, acc2[n][0]);
                acc2[n][1] = fma2(xx, wp1, acc2[n][1]);
            }
        }
        __syncthreads();
    }

    // Second half: K in [128,256) from AggS (already in smem)
    for (int k0 = 0; k0 < D_FEAT; k0 += KC) {
        {
            const float4* src = reinterpret_cast<const float4*>(W + (D_FEAT + k0) * D_FEAT);
            float4* dst = reinterpret_cast<float4*>(Ws);
            dst[tid]       = src[tid];
            dst[tid + 256] = src[tid + 256];
        }
        __syncthreads();
        #pragma unroll
        for (int kk = 0; kk < KC; kk++) {
            const unsigned long long* wrow =
                reinterpret_cast<const unsigned long long*>(&Ws[kk * D_FEAT + lane * 4]);
            unsigned long long wp0 = wrow[0];
            unsigned long long wp1 = wrow[1];
            #pragma unroll
            for (int n = 0; n < 2; n++) {
                unsigned long long xx = dup2(AggS[(wid * 2 + n) * D_FEAT + k0 + kk]);
                acc2[n][0] = fma2(xx, wp0, acc2[n][0]);
                acc2[n][1] = fma2(xx, wp1, acc2[n][1]);
            }
        }
        __syncthreads();
    }

    // Epilogue: unpack, add bias, store
    float4 bb = *reinterpret_cast<const float4*>(&b[lane * 4]);
    #pragma unroll
    for (int n = 0; n < 2; n++) {
        int gn = n0 + wid * 2 + n;
        if (gn < N_NODES) {
            float2 p0 = *reinterpret_cast<float2*>(&acc2[n][0]);
            float2 p1 = *reinterpret_cast<float2*>(&acc2[n][1]);
            float4 r;
            r.x = p0.x + bb.x;
            r.y = p0.y + bb.y;
            r.z = p1.x + bb.z;
            r.w = p1.y + bb.w;
            *reinterpret_cast<float4*>(out + (size_t)gn * D_FEAT + lane * 4) = r;
        }
    }
}

// ---------------------------------------------------------------------------
extern "C" void kernel_launch(void* const* d_in, const int* in_sizes, int n_in,
                              void* d_out, int out_size) {
    const float* edge_feat = (const float*)d_in[0];
    const float* node_feat = (const float*)d_in[1];
    const int*   recv_idx  = (const int*)d_in[2];
    const float* W         = (const float*)d_in[3];
    const float* b         = (const float*)d_in[4];
    float*       out       = (float*)d_out;

    fill_kernel<<<(N_EDGES / 4 + 255) / 256, 256>>>(recv_idx);

    int blocks = (N_NODES + NT - 1) / NT;   // 625
    fused_kernel<<<blocks, 256>>>(edge_feat, node_feat, W, b, out);
}